// round 14
// baseline (speedup 1.0000x reference)
#include <cuda_runtime.h>
#include <cstdint>

#define N_NODES 4096
#define F_IN    512
#define HD1     64
#define NH1     8
#define C2      16
#define MAXDEG  256

__device__ int   g_nbr[N_NODES * MAXDEG];
__device__ int   g_deg[N_NODES];
__device__ float g_h1 [N_NODES * HD1];
__device__ float g_es1[N_NODES * NH1];
__device__ float g_ed1[N_NODES * NH1];
__device__ float g_h2 [N_NODES * C2];
__device__ float g_es2[N_NODES];
__device__ float g_ed2[N_NODES];

// ---------------------------------------------------------------------------
// K1: GEMM1 h1 = x @ W1 + fused es1/ed1 epilogue. Double-buffered.
// 512 threads/block (16 warps/SM vs 8 -> 2x latency cover at grid=128).
// Each thread: 1 row x 4 cols.
// ---------------------------------------------------------------------------
__global__ __launch_bounds__(512) void k_gemm1(const float* __restrict__ X,
                                               const float* __restrict__ W,
                                               const float* __restrict__ a_src,
                                               const float* __restrict__ a_dst)
{
    __shared__ float As[2][32][33];
    __shared__ float Bs[2][32][64];

    const int tid = threadIdx.x;
    const int tx  = tid & 15;        // col group: cols tx*4..tx*4+3
    const int ty  = tid >> 4;        // row 0..31
    const int m0  = blockIdx.x * 32;

    // load coords
    const int ar  = tid >> 3;        // A row (threads < 256)
    const int ac4 = tid & 7;         // A col4
    const int br  = tid >> 4;        // B row 0..31
    const int bc4 = tid & 15;        // B col4 0..15

    float4 acc = make_float4(0.f, 0.f, 0.f, 0.f);

    // preload tile 0
    if (tid < 256) {
        float4 va = *(const float4*)(X + (size_t)(m0 + ar) * F_IN + ac4 * 4);
        As[0][ac4 * 4 + 0][ar] = va.x;
        As[0][ac4 * 4 + 1][ar] = va.y;
        As[0][ac4 * 4 + 2][ar] = va.z;
        As[0][ac4 * 4 + 3][ar] = va.w;
    }
    *(float4*)(&Bs[0][br][bc4 * 4]) =
        *(const float4*)(W + (size_t)br * HD1 + bc4 * 4);
    __syncthreads();

    #pragma unroll 1
    for (int t = 0; t < 16; t++) {
        const int cur = t & 1;
        const int nxt = cur ^ 1;

        float4 va, vb;
        if (t < 15) {
            const int kt = (t + 1) * 32;
            if (tid < 256)
                va = *(const float4*)(X + (size_t)(m0 + ar) * F_IN + kt + ac4 * 4);
            vb = *(const float4*)(W + (size_t)(kt + br) * HD1 + bc4 * 4);
        }

        #pragma unroll
        for (int k = 0; k < 32; k++) {
            float a  = As[cur][k][ty];
            float4 b = *(const float4*)(&Bs[cur][k][tx * 4]);
            acc.x += a * b.x;
            acc.y += a * b.y;
            acc.z += a * b.z;
            acc.w += a * b.w;
        }

        if (t < 15) {
            if (tid < 256) {
                As[nxt][ac4 * 4 + 0][ar] = va.x;
                As[nxt][ac4 * 4 + 1][ar] = va.y;
                As[nxt][ac4 * 4 + 2][ar] = va.z;
                As[nxt][ac4 * 4 + 3][ar] = va.w;
            }
            *(float4*)(&Bs[nxt][br][bc4 * 4]) = vb;
        }
        __syncthreads();
    }

    const int row = m0 + ty;
    *(float4*)(g_h1 + (size_t)row * HD1 + tx * 4) = acc;

    // fused scores: head h = tx>>1 (4 cols per thread lie in one head half)
    float4 ws = *(const float4*)(a_src + tx * 4);
    float4 wd = *(const float4*)(a_dst + tx * 4);
    float s = acc.x * ws.x + acc.y * ws.y + acc.z * ws.z + acc.w * ws.w;
    float d = acc.x * wd.x + acc.y * wd.y + acc.z * wd.z + acc.w * wd.w;
    // partner = lane^1 (tx^1, same ty)
    s += __shfl_xor_sync(0xFFFFFFFFu, s, 1);
    d += __shfl_xor_sync(0xFFFFFFFFu, d, 1);
    if ((tx & 1) == 0) {
        int h = tx >> 1;
        g_es1[row * NH1 + h] = s;
        g_ed1[row * NH1 + h] = d;
    }
}

// ---------------------------------------------------------------------------
// K2: FUSED adjacency-scan + layer-1 attention + ELU + layer-2 row + scores.
// 1 block/row, 64 threads (round-13, measured-neutral-best, unchanged).
// ---------------------------------------------------------------------------
__global__ __launch_bounds__(64) void k_attn1(const void* __restrict__ adj,
                                              const float* __restrict__ W2,
                                              const float* __restrict__ a2_src,
                                              const float* __restrict__ a2_dst)
{
    const int i    = blockIdx.x;
    const int tid  = threadIdx.x;
    const int lane = tid & 31;
    const int wid  = tid >> 5;
    const uint8_t* u8 = (const uint8_t*)adj;

    __shared__ int   snbr[MAXDEG];
    __shared__ float ew[MAXDEG * NH1];
    __shared__ float red[2][NH1];
    __shared__ float ssv[NH1];
    __shared__ float sa1[HD1];
    __shared__ int   wsum[2];

    // ---- phase 0: scan adjacency row i ----
    int fmt;
    if (u8[(size_t)N_NODES + 1] == 1)            fmt = 0;
    else if (u8[4 * ((size_t)N_NODES + 1)] == 1) fmt = 1;
    else                                         fmt = 2;

    uint64_t mask = 0;
    #pragma unroll
    for (int r = 0; r < 16; r++) {
        const int cbase = (r * 64 + tid) * 4;
        uint64_t p0, p1, p2, p3;
        if (fmt == 2) {
            float4 v = *(const float4*)((const float*)adj + (size_t)i * N_NODES + cbase);
            p0 = v.x != 0.f; p1 = v.y != 0.f; p2 = v.z != 0.f; p3 = v.w != 0.f;
        } else if (fmt == 1) {
            int4 v = *(const int4*)((const int*)adj + (size_t)i * N_NODES + cbase);
            p0 = v.x != 0; p1 = v.y != 0; p2 = v.z != 0; p3 = v.w != 0;
        } else {
            uint32_t w = *(const uint32_t*)(u8 + (size_t)i * N_NODES + cbase);
            p0 = (w & 0x000000FFu) != 0;
            p1 = (w & 0x0000FF00u) != 0;
            p2 = (w & 0x00FF0000u) != 0;
            p3 = (w & 0xFF000000u) != 0;
        }
        mask |= (p0 << (r * 4)) | (p1 << (r * 4 + 1)) |
                (p2 << (r * 4 + 2)) | (p3 << (r * 4 + 3));
    }
    const int cnt = (int)__popcll(mask);

    int incl = cnt;
    #pragma unroll
    for (int o = 1; o < 32; o <<= 1) {
        int t = __shfl_up_sync(0xFFFFFFFFu, incl, o);
        if (lane >= o) incl += t;
    }
    if (lane == 31) wsum[wid] = incl;
    __syncthreads();
    const int total = wsum[0] + wsum[1];
    const int deg   = (total > MAXDEG) ? MAXDEG : total;
    if (tid == 0) g_deg[i] = deg;

    {
        int base = ((wid == 1) ? wsum[0] : 0) + (incl - cnt);
        int* gout = g_nbr + (size_t)i * MAXDEG;
        #pragma unroll
        for (int r = 0; r < 16; r++) {
            const int cbase = (r * 64 + tid) * 4;
            #pragma unroll
            for (int q = 0; q < 4; q++) {
                if ((mask >> (r * 4 + q)) & 1ull) {
                    if (base < MAXDEG) {
                        snbr[base] = cbase + q;
                        gout[base] = cbase + q;
                    }
                    base++;
                }
            }
        }
    }
    __syncthreads();

    // ---- phase 1: fill w = exp(leakyrelu(e)) + sum partials ----
    const int h  = tid & 7;
    const int wh = tid >> 5;
    const int tot = deg * NH1;
    const float esi_h = g_es1[i * NH1 + h];

    float sloc = 0.f;
    for (int idx = tid; idx < tot; idx += 64) {
        int j = idx >> 3;
        float e = esi_h + g_ed1[snbr[j] * NH1 + h];
        e = (e > 0.f) ? e : 0.2f * e;
        float w = __expf(e);
        ew[idx] = w;
        sloc += w;
    }
    sloc += __shfl_xor_sync(0xFFFFFFFFu, sloc, 8);
    sloc += __shfl_xor_sync(0xFFFFFFFFu, sloc, 16);
    if ((tid & 31) < 8) red[wh][h] = sloc;
    __syncthreads();
    if (tid < NH1) ssv[tid] = 1.f / (red[0][tid] + red[1][tid]);
    __syncthreads();

    // ---- phase 2: gather (thread = output column), ELU ----
    {
        const int hh = tid >> 3;
        const float inv = ssv[hh];
        float a0 = 0.f, a1 = 0.f, a2 = 0.f, a3 = 0.f;
        int j = 0;
        for (; j + 4 <= deg; j += 4) {
            a0 += ew[(j+0) * NH1 + hh] * g_h1[(size_t)snbr[j+0] * HD1 + tid];
            a1 += ew[(j+1) * NH1 + hh] * g_h1[(size_t)snbr[j+1] * HD1 + tid];
            a2 += ew[(j+2) * NH1 + hh] * g_h1[(size_t)snbr[j+2] * HD1 + tid];
            a3 += ew[(j+3) * NH1 + hh] * g_h1[(size_t)snbr[j+3] * HD1 + tid];
        }
        for (; j < deg; j++)
            a0 += ew[j * NH1 + hh] * g_h1[(size_t)snbr[j] * HD1 + tid];
        float acc = ((a0 + a1) + (a2 + a3)) * inv;
        acc = (acc > 0.f) ? acc : expm1f(acc);   // ELU
        sa1[tid] = acc;
    }
    __syncthreads();

    // ---- phase 3: fused layer-2 row + es2/ed2 ----
    if (tid < C2) {
        float v = 0.f;
        #pragma unroll 8
        for (int k = 0; k < HD1; k++)
            v += sa1[k] * __ldg(&W2[k * C2 + tid]);
        g_h2[(size_t)i * C2 + tid] = v;

        float s = v * a2_src[tid];
        float d = v * a2_dst[tid];
        #pragma unroll
        for (int o = 8; o >= 1; o >>= 1) {
            s += __shfl_xor_sync(0x0000FFFFu, s, o);
            d += __shfl_xor_sync(0x0000FFFFu, d, o);
        }
        if (tid == 0) {
            g_es2[i] = s;
            g_ed2[i] = d;
        }
    }
}

// ---------------------------------------------------------------------------
// K3: layer-2 sparse attention. Single fused pass (round-11 best, unchanged).
// ---------------------------------------------------------------------------
__global__ __launch_bounds__(256) void k_attn2(float* __restrict__ out)
{
    const int w    = threadIdx.x >> 5;
    const int lane = threadIdx.x & 31;
    const int i    = blockIdx.x * 8 + w;
    const int deg  = g_deg[i];

    __shared__ int snbr[8][MAXDEG];

    for (int j = lane; j < deg; j += 32)
        snbr[w][j] = g_nbr[(size_t)i * MAXDEG + j];
    __syncwarp();

    const float esi = g_es2[i];
    const int g  = lane >> 2;
    const int c4 = lane & 3;

    float4 acc = make_float4(0.f, 0.f, 0.f, 0.f);
    float  wsum = 0.f;
    for (int base = 0; base < deg; base += 8) {
        int j = base + g;
        if (j < deg) {
            int   n  = snbr[w][j];
            float e  = esi + g_ed2[n];
            e = (e > 0.f) ? e : 0.2f * e;
            float wt = __expf(e);
            float4 v = *(const float4*)(g_h2 + (size_t)n * C2 + c4 * 4);
            acc.x += wt * v.x;
            acc.y += wt * v.y;
            acc.z += wt * v.z;
            acc.w += wt * v.w;
            wsum  += wt;
        }
    }
    #pragma unroll
    for (int o = 4; o <= 16; o <<= 1) {
        acc.x += __shfl_xor_sync(0xFFFFFFFFu, acc.x, o);
        acc.y += __shfl_xor_sync(0xFFFFFFFFu, acc.y, o);
        acc.z += __shfl_xor_sync(0xFFFFFFFFu, acc.z, o);
        acc.w += __shfl_xor_sync(0xFFFFFFFFu, acc.w, o);
        wsum  += __shfl_xor_sync(0xFFFFFFFFu, wsum,  o);
    }
    if (lane < 4) {
        const float inv = 1.f / wsum;
        float4 r = make_float4(acc.x * inv, acc.y * inv, acc.z * inv, acc.w * inv);
        *(float4*)(out + (size_t)i * C2 + lane * 4) = r;
    }
}

// ---------------------------------------------------------------------------
// Launch: strictly sequential on the capture stream. 3 kernels.
// ---------------------------------------------------------------------------
extern "C" void kernel_launch(void* const* d_in, const int* in_sizes, int n_in,
                              void* d_out, int out_size)
{
    const float* x      = (const float*)d_in[0];
    const void*  adj    = d_in[1];
    const float* W1     = (const float*)d_in[2];
    const float* a1_src = (const float*)d_in[3];
    const float* a1_dst = (const float*)d_in[4];
    const float* W2     = (const float*)d_in[5];
    const float* a2_src = (const float*)d_in[6];
    const float* a2_dst = (const float*)d_in[7];
    float* out = (float*)d_out;

    k_gemm1<<<N_NODES / 32, 512>>>(x, W1, a1_src, a1_dst);
    k_attn1<<<N_NODES, 64>>>(adj, W2, a2_src, a2_dst);
    k_attn2<<<N_NODES / 8, 256>>>(out);
}

// round 15
// speedup vs baseline: 1.2749x; 1.2749x over previous
#include <cuda_runtime.h>
#include <cstdint>

#define N_NODES 4096
#define F_IN    512
#define HD1     64
#define NH1     8
#define C2      16
#define MAXDEG  256
#define KSPLIT  2
#define KHALF   (F_IN / KSPLIT)      // 256
#define MBLOCKS (N_NODES / 32)       // 128

__device__ int   g_nbr[N_NODES * MAXDEG];
__device__ int   g_deg[N_NODES];
__device__ float g_h1 [N_NODES * HD1];
__device__ float g_h1p[KSPLIT][N_NODES * HD1];
__device__ float g_es1[N_NODES * NH1];
__device__ float g_ed1[N_NODES * NH1];
__device__ float g_es1p[KSPLIT][N_NODES * NH1];
__device__ float g_ed1p[KSPLIT][N_NODES * NH1];
__device__ float g_h2 [N_NODES * C2];
__device__ float g_es2[N_NODES];
__device__ float g_ed2[N_NODES];

// ---------------------------------------------------------------------------
// K1: split-K GEMM1. 256 blocks = 128 M-tiles x 2 K-halves. Round-13 block
// internals (2 rows x 4 cols/thread, double-buffered). Two blocks co-reside
// per SM -> 16 warps/SM with the good LDS:FFMA mix.
// Scores are linear in acc -> partial scores per half, summed in k_combine.
// ---------------------------------------------------------------------------
__global__ __launch_bounds__(256) void k_gemm1(const float* __restrict__ X,
                                               const float* __restrict__ W,
                                               const float* __restrict__ a_src,
                                               const float* __restrict__ a_dst)
{
    __shared__ float As[2][32][33];
    __shared__ float Bs[2][32][64];

    const int tid = threadIdx.x;
    const int tx  = tid & 15;
    const int ty  = tid >> 4;
    const int bk  = blockIdx.x >> 7;            // K-half
    const int m0  = (blockIdx.x & 127) * 32;
    const int k0  = bk * KHALF;

    const int ar  = tid >> 3;
    const int ac4 = tid & 7;
    const int br  = tid >> 4;
    const int bc4 = tid & 15;

    float acc[2][4] = {};

    {
        float4 va = *(const float4*)(X + (size_t)(m0 + ar) * F_IN + k0 + ac4 * 4);
        As[0][ac4 * 4 + 0][ar] = va.x;
        As[0][ac4 * 4 + 1][ar] = va.y;
        As[0][ac4 * 4 + 2][ar] = va.z;
        As[0][ac4 * 4 + 3][ar] = va.w;
        float4 vb0 = *(const float4*)(W + (size_t)(k0 + br) * HD1 + bc4 * 4);
        float4 vb1 = *(const float4*)(W + (size_t)(k0 + br + 16) * HD1 + bc4 * 4);
        *(float4*)(&Bs[0][br][bc4 * 4])      = vb0;
        *(float4*)(&Bs[0][br + 16][bc4 * 4]) = vb1;
    }
    __syncthreads();

    #pragma unroll 1
    for (int t = 0; t < KHALF / 32; t++) {
        const int cur = t & 1;
        const int nxt = cur ^ 1;

        float4 va, vb0, vb1;
        if (t < KHALF / 32 - 1) {
            const int kt = k0 + (t + 1) * 32;
            va  = *(const float4*)(X + (size_t)(m0 + ar) * F_IN + kt + ac4 * 4);
            vb0 = *(const float4*)(W + (size_t)(kt + br) * HD1 + bc4 * 4);
            vb1 = *(const float4*)(W + (size_t)(kt + br + 16) * HD1 + bc4 * 4);
        }

        #pragma unroll
        for (int k = 0; k < 32; k++) {
            float a0 = As[cur][k][ty * 2 + 0];
            float a1 = As[cur][k][ty * 2 + 1];
            float4 b = *(const float4*)(&Bs[cur][k][tx * 4]);
            acc[0][0] += a0 * b.x; acc[0][1] += a0 * b.y;
            acc[0][2] += a0 * b.z; acc[0][3] += a0 * b.w;
            acc[1][0] += a1 * b.x; acc[1][1] += a1 * b.y;
            acc[1][2] += a1 * b.z; acc[1][3] += a1 * b.w;
        }

        if (t < KHALF / 32 - 1) {
            As[nxt][ac4 * 4 + 0][ar] = va.x;
            As[nxt][ac4 * 4 + 1][ar] = va.y;
            As[nxt][ac4 * 4 + 2][ar] = va.z;
            As[nxt][ac4 * 4 + 3][ar] = va.w;
            *(float4*)(&Bs[nxt][br][bc4 * 4])      = vb0;
            *(float4*)(&Bs[nxt][br + 16][bc4 * 4]) = vb1;
        }
        __syncthreads();
    }

    float* h1p = g_h1p[bk];
    #pragma unroll
    for (int u = 0; u < 2; u++) {
        float4 v = make_float4(acc[u][0], acc[u][1], acc[u][2], acc[u][3]);
        *(float4*)(h1p + (size_t)(m0 + ty * 2 + u) * HD1 + tx * 4) = v;
    }

    float4 ws = *(const float4*)(a_src + tx * 4);
    float4 wd = *(const float4*)(a_dst + tx * 4);
    float s0 = acc[0][0]*ws.x + acc[0][1]*ws.y + acc[0][2]*ws.z + acc[0][3]*ws.w;
    float s1 = acc[1][0]*ws.x + acc[1][1]*ws.y + acc[1][2]*ws.z + acc[1][3]*ws.w;
    float d0 = acc[0][0]*wd.x + acc[0][1]*wd.y + acc[0][2]*wd.z + acc[0][3]*wd.w;
    float d1 = acc[1][0]*wd.x + acc[1][1]*wd.y + acc[1][2]*wd.z + acc[1][3]*wd.w;
    s0 += __shfl_xor_sync(0xFFFFFFFFu, s0, 1);
    s1 += __shfl_xor_sync(0xFFFFFFFFu, s1, 1);
    d0 += __shfl_xor_sync(0xFFFFFFFFu, d0, 1);
    d1 += __shfl_xor_sync(0xFFFFFFFFu, d1, 1);
    if ((tx & 1) == 0) {
        int h = tx >> 1;
        g_es1p[bk][(m0 + ty * 2 + 0) * NH1 + h] = s0;
        g_es1p[bk][(m0 + ty * 2 + 1) * NH1 + h] = s1;
        g_ed1p[bk][(m0 + ty * 2 + 0) * NH1 + h] = d0;
        g_ed1p[bk][(m0 + ty * 2 + 1) * NH1 + h] = d1;
    }
}

// ---------------------------------------------------------------------------
// K1b: combine the two K-halves (h1 + scores). 128 blocks x 256 threads.
// ---------------------------------------------------------------------------
__global__ __launch_bounds__(256) void k_combine()
{
    const int idx = blockIdx.x * 256 + threadIdx.x;   // 0..32767

    // h1: 65536 float4 units -> 2 per thread
    #pragma unroll
    for (int u = 0; u < 2; u++) {
        int id = idx * 2 + u;
        float4 a = *(const float4*)(&g_h1p[0][id * 4]);
        float4 b = *(const float4*)(&g_h1p[1][id * 4]);
        float4 r = make_float4(a.x + b.x, a.y + b.y, a.z + b.z, a.w + b.w);
        *(float4*)(&g_h1[id * 4]) = r;
    }
    // scores: exactly N*NH1 = 32768 values -> 1 per thread
    g_es1[idx] = g_es1p[0][idx] + g_es1p[1][idx];
    g_ed1[idx] = g_ed1p[0][idx] + g_ed1p[1][idx];
}

// ---------------------------------------------------------------------------
// K2: FUSED adjacency-scan + layer-1 attention + ELU + layer-2 row + scores.
// (round-13, unchanged)
// ---------------------------------------------------------------------------
__global__ __launch_bounds__(64) void k_attn1(const void* __restrict__ adj,
                                              const float* __restrict__ W2,
                                              const float* __restrict__ a2_src,
                                              const float* __restrict__ a2_dst)
{
    const int i    = blockIdx.x;
    const int tid  = threadIdx.x;
    const int lane = tid & 31;
    const int wid  = tid >> 5;
    const uint8_t* u8 = (const uint8_t*)adj;

    __shared__ int   snbr[MAXDEG];
    __shared__ float ew[MAXDEG * NH1];
    __shared__ float red[2][NH1];
    __shared__ float ssv[NH1];
    __shared__ float sa1[HD1];
    __shared__ int   wsum[2];

    int fmt;
    if (u8[(size_t)N_NODES + 1] == 1)            fmt = 0;
    else if (u8[4 * ((size_t)N_NODES + 1)] == 1) fmt = 1;
    else                                         fmt = 2;

    uint64_t mask = 0;
    #pragma unroll
    for (int r = 0; r < 16; r++) {
        const int cbase = (r * 64 + tid) * 4;
        uint64_t p0, p1, p2, p3;
        if (fmt == 2) {
            float4 v = *(const float4*)((const float*)adj + (size_t)i * N_NODES + cbase);
            p0 = v.x != 0.f; p1 = v.y != 0.f; p2 = v.z != 0.f; p3 = v.w != 0.f;
        } else if (fmt == 1) {
            int4 v = *(const int4*)((const int*)adj + (size_t)i * N_NODES + cbase);
            p0 = v.x != 0; p1 = v.y != 0; p2 = v.z != 0; p3 = v.w != 0;
        } else {
            uint32_t w = *(const uint32_t*)(u8 + (size_t)i * N_NODES + cbase);
            p0 = (w & 0x000000FFu) != 0;
            p1 = (w & 0x0000FF00u) != 0;
            p2 = (w & 0x00FF0000u) != 0;
            p3 = (w & 0xFF000000u) != 0;
        }
        mask |= (p0 << (r * 4)) | (p1 << (r * 4 + 1)) |
                (p2 << (r * 4 + 2)) | (p3 << (r * 4 + 3));
    }
    const int cnt = (int)__popcll(mask);

    int incl = cnt;
    #pragma unroll
    for (int o = 1; o < 32; o <<= 1) {
        int t = __shfl_up_sync(0xFFFFFFFFu, incl, o);
        if (lane >= o) incl += t;
    }
    if (lane == 31) wsum[wid] = incl;
    __syncthreads();
    const int total = wsum[0] + wsum[1];
    const int deg   = (total > MAXDEG) ? MAXDEG : total;
    if (tid == 0) g_deg[i] = deg;

    {
        int base = ((wid == 1) ? wsum[0] : 0) + (incl - cnt);
        int* gout = g_nbr + (size_t)i * MAXDEG;
        #pragma unroll
        for (int r = 0; r < 16; r++) {
            const int cbase = (r * 64 + tid) * 4;
            #pragma unroll
            for (int q = 0; q < 4; q++) {
                if ((mask >> (r * 4 + q)) & 1ull) {
                    if (base < MAXDEG) {
                        snbr[base] = cbase + q;
                        gout[base] = cbase + q;
                    }
                    base++;
                }
            }
        }
    }
    __syncthreads();

    const int h  = tid & 7;
    const int wh = tid >> 5;
    const int tot = deg * NH1;
    const float esi_h = g_es1[i * NH1 + h];

    float sloc = 0.f;
    for (int idx = tid; idx < tot; idx += 64) {
        int j = idx >> 3;
        float e = esi_h + g_ed1[snbr[j] * NH1 + h];
        e = (e > 0.f) ? e : 0.2f * e;
        float w = __expf(e);
        ew[idx] = w;
        sloc += w;
    }
    sloc += __shfl_xor_sync(0xFFFFFFFFu, sloc, 8);
    sloc += __shfl_xor_sync(0xFFFFFFFFu, sloc, 16);
    if ((tid & 31) < 8) red[wh][h] = sloc;
    __syncthreads();
    if (tid < NH1) ssv[tid] = 1.f / (red[0][tid] + red[1][tid]);
    __syncthreads();

    {
        const int hh = tid >> 3;
        const float inv = ssv[hh];
        float a0 = 0.f, a1 = 0.f, a2 = 0.f, a3 = 0.f;
        int j = 0;
        for (; j + 4 <= deg; j += 4) {
            a0 += ew[(j+0) * NH1 + hh] * g_h1[(size_t)snbr[j+0] * HD1 + tid];
            a1 += ew[(j+1) * NH1 + hh] * g_h1[(size_t)snbr[j+1] * HD1 + tid];
            a2 += ew[(j+2) * NH1 + hh] * g_h1[(size_t)snbr[j+2] * HD1 + tid];
            a3 += ew[(j+3) * NH1 + hh] * g_h1[(size_t)snbr[j+3] * HD1 + tid];
        }
        for (; j < deg; j++)
            a0 += ew[j * NH1 + hh] * g_h1[(size_t)snbr[j] * HD1 + tid];
        float acc = ((a0 + a1) + (a2 + a3)) * inv;
        acc = (acc > 0.f) ? acc : expm1f(acc);   // ELU
        sa1[tid] = acc;
    }
    __syncthreads();

    if (tid < C2) {
        float v = 0.f;
        #pragma unroll 8
        for (int k = 0; k < HD1; k++)
            v += sa1[k] * __ldg(&W2[k * C2 + tid]);
        g_h2[(size_t)i * C2 + tid] = v;

        float s = v * a2_src[tid];
        float d = v * a2_dst[tid];
        #pragma unroll
        for (int o = 8; o >= 1; o >>= 1) {
            s += __shfl_xor_sync(0x0000FFFFu, s, o);
            d += __shfl_xor_sync(0x0000FFFFu, d, o);
        }
        if (tid == 0) {
            g_es2[i] = s;
            g_ed2[i] = d;
        }
    }
}

// ---------------------------------------------------------------------------
// K3: layer-2 sparse attention. Single fused pass (unchanged).
// ---------------------------------------------------------------------------
__global__ __launch_bounds__(256) void k_attn2(float* __restrict__ out)
{
    const int w    = threadIdx.x >> 5;
    const int lane = threadIdx.x & 31;
    const int i    = blockIdx.x * 8 + w;
    const int deg  = g_deg[i];

    __shared__ int snbr[8][MAXDEG];

    for (int j = lane; j < deg; j += 32)
        snbr[w][j] = g_nbr[(size_t)i * MAXDEG + j];
    __syncwarp();

    const float esi = g_es2[i];
    const int g  = lane >> 2;
    const int c4 = lane & 3;

    float4 acc = make_float4(0.f, 0.f, 0.f, 0.f);
    float  wsum = 0.f;
    for (int base = 0; base < deg; base += 8) {
        int j = base + g;
        if (j < deg) {
            int   n  = snbr[w][j];
            float e  = esi + g_ed2[n];
            e = (e > 0.f) ? e : 0.2f * e;
            float wt = __expf(e);
            float4 v = *(const float4*)(g_h2 + (size_t)n * C2 + c4 * 4);
            acc.x += wt * v.x;
            acc.y += wt * v.y;
            acc.z += wt * v.z;
            acc.w += wt * v.w;
            wsum  += wt;
        }
    }
    #pragma unroll
    for (int o = 4; o <= 16; o <<= 1) {
        acc.x += __shfl_xor_sync(0xFFFFFFFFu, acc.x, o);
        acc.y += __shfl_xor_sync(0xFFFFFFFFu, acc.y, o);
        acc.z += __shfl_xor_sync(0xFFFFFFFFu, acc.z, o);
        acc.w += __shfl_xor_sync(0xFFFFFFFFu, acc.w, o);
        wsum  += __shfl_xor_sync(0xFFFFFFFFu, wsum,  o);
    }
    if (lane < 4) {
        const float inv = 1.f / wsum;
        float4 r = make_float4(acc.x * inv, acc.y * inv, acc.z * inv, acc.w * inv);
        *(float4*)(out + (size_t)i * C2 + lane * 4) = r;
    }
}

// ---------------------------------------------------------------------------
// Launch: strictly sequential on the capture stream. 4 kernels.
// ---------------------------------------------------------------------------
extern "C" void kernel_launch(void* const* d_in, const int* in_sizes, int n_in,
                              void* d_out, int out_size)
{
    const float* x      = (const float*)d_in[0];
    const void*  adj    = d_in[1];
    const float* W1     = (const float*)d_in[2];
    const float* a1_src = (const float*)d_in[3];
    const float* a1_dst = (const float*)d_in[4];
    const float* W2     = (const float*)d_in[5];
    const float* a2_src = (const float*)d_in[6];
    const float* a2_dst = (const float*)d_in[7];
    float* out = (float*)d_out;

    k_gemm1  <<<MBLOCKS * KSPLIT, 256>>>(x, W1, a1_src, a1_dst);
    k_combine<<<N_NODES * NH1 / 256, 256>>>();
    k_attn1  <<<N_NODES, 64>>>(adj, W2, a2_src, a2_dst);
    k_attn2  <<<N_NODES / 8, 256>>>(out);
}

// round 16
// speedup vs baseline: 1.4944x; 1.1722x over previous
#include <cuda_runtime.h>
#include <cstdint>

#define N_NODES 4096
#define F_IN    512
#define HD1     64
#define NH1     8
#define C2      16
#define MAXDEG  256

#define SA 36     // A smem row stride (m-major): bank = 4g+t, conflict-free
#define SB 72     // B smem row stride (k-major): bank = 8t+g, conflict-free

__device__ int   g_nbr[N_NODES * MAXDEG];
__device__ int   g_deg[N_NODES];
__device__ float g_h1 [N_NODES * HD1];
__device__ float g_es1[N_NODES * NH1];
__device__ float g_ed1[N_NODES * NH1];
__device__ float g_h2 [N_NODES * C2];
__device__ float g_es2[N_NODES];
__device__ float g_ed2[N_NODES];

// ---------------------------------------------------------------------------
// tf32 helpers
// ---------------------------------------------------------------------------
__device__ __forceinline__ uint32_t f2tf32(float x)
{
    uint32_t r;
    asm("cvt.rna.tf32.f32 %0, %1;" : "=r"(r) : "f"(x));
    return r;
}
__device__ __forceinline__ void cvt_split(float x, float& hi, float& lo)
{
    hi = __uint_as_float(f2tf32(x));
    lo = __uint_as_float(f2tf32(x - hi));
}

#define MMA_TF32(c, A0, A1, A2, A3, B0, B1)                                   \
    asm volatile(                                                             \
        "mma.sync.aligned.m16n8k8.row.col.f32.tf32.tf32.f32 "                 \
        "{%0,%1,%2,%3}, {%4,%5,%6,%7}, {%8,%9}, {%0,%1,%2,%3};"               \
        : "+f"(c[0]), "+f"(c[1]), "+f"(c[2]), "+f"(c[3])                      \
        : "r"(A0), "r"(A1), "r"(A2), "r"(A3), "r"(B0), "r"(B1))

// ---------------------------------------------------------------------------
// K1: GEMM1 h1 = x @ W1 via tensor cores (tf32, 3xTF32 split precision).
// grid=128, 256 thr (8 warps = 2x4 warp-tiles of 16x16). Double-buffered
// reg-prefetch. Fused es1/ed1 epilogue (linear in acc -> exact).
// ---------------------------------------------------------------------------
__global__ __launch_bounds__(256) void k_gemm1(const float* __restrict__ X,
                                               const float* __restrict__ W,
                                               const float* __restrict__ a_src,
                                               const float* __restrict__ a_dst)
{
    __shared__ float sAh[2][32 * SA];   // A hi, [m][k], stride SA
    __shared__ float sAl[2][32 * SA];
    __shared__ float sBh[2][32 * SB];   // B hi, [k][n], stride SB
    __shared__ float sBl[2][32 * SB];

    const int tid  = threadIdx.x;
    const int lane = tid & 31;
    const int wrp  = tid >> 5;          // 0..7
    const int wm   = wrp >> 2;          // 0..1  (m 16-row half)
    const int wn   = wrp & 3;           // 0..3  (n 16-col quarter)
    const int m0   = blockIdx.x * 32;

    const int g = lane >> 2;            // 0..7
    const int t = lane & 3;             // 0..3

    // loader coords
    const int ar  = tid >> 3;           // A row 0..31
    const int ac4 = tid & 7;            // A k-chunk 0..7
    const int br  = tid >> 4;           // B row 0..15 (+16)
    const int bc4 = tid & 15;           // B n-chunk 0..15

    float acc[2][4] = {};               // [n8 tile][c0..c3]

    // ---- preload tile 0 (load + split + store) ----
    {
        float4 va = *(const float4*)(X + (size_t)(m0 + ar) * F_IN + ac4 * 4);
        float h0,l0,h1,l1,h2,l2,h3,l3;
        cvt_split(va.x, h0, l0); cvt_split(va.y, h1, l1);
        cvt_split(va.z, h2, l2); cvt_split(va.w, h3, l3);
        float* ah = &sAh[0][ar * SA + ac4 * 4];
        float* al = &sAl[0][ar * SA + ac4 * 4];
        ah[0]=h0; ah[1]=h1; ah[2]=h2; ah[3]=h3;
        al[0]=l0; al[1]=l1; al[2]=l2; al[3]=l3;

        float4 vb0 = *(const float4*)(W + (size_t)br * HD1 + bc4 * 4);
        float4 vb1 = *(const float4*)(W + (size_t)(br + 16) * HD1 + bc4 * 4);
        cvt_split(vb0.x, h0, l0); cvt_split(vb0.y, h1, l1);
        cvt_split(vb0.z, h2, l2); cvt_split(vb0.w, h3, l3);
        float* bh = &sBh[0][br * SB + bc4 * 4];
        float* bl = &sBl[0][br * SB + bc4 * 4];
        bh[0]=h0; bh[1]=h1; bh[2]=h2; bh[3]=h3;
        bl[0]=l0; bl[1]=l1; bl[2]=l2; bl[3]=l3;
        cvt_split(vb1.x, h0, l0); cvt_split(vb1.y, h1, l1);
        cvt_split(vb1.z, h2, l2); cvt_split(vb1.w, h3, l3);
        bh = &sBh[0][(br + 16) * SB + bc4 * 4];
        bl = &sBl[0][(br + 16) * SB + bc4 * 4];
        bh[0]=h0; bh[1]=h1; bh[2]=h2; bh[3]=h3;
        bl[0]=l0; bl[1]=l1; bl[2]=l2; bl[3]=l3;
    }
    __syncthreads();

    const int rowA = wm * 16 + g;       // A frag rows rowA, rowA+8
    const int colB = wn * 16 + g;       // B frag col (tile0); tile1 at +8

    #pragma unroll 1
    for (int tt = 0; tt < 16; tt++) {
        const int cur = tt & 1;
        const int nxt = cur ^ 1;

        // prefetch next tile into regs
        float4 va, vb0, vb1;
        if (tt < 15) {
            const int kt = (tt + 1) * 32;
            va  = *(const float4*)(X + (size_t)(m0 + ar) * F_IN + kt + ac4 * 4);
            vb0 = *(const float4*)(W + (size_t)(kt + br) * HD1 + bc4 * 4);
            vb1 = *(const float4*)(W + (size_t)(kt + br + 16) * HD1 + bc4 * 4);
        }

        // mma phase over current tile: 4 k8-steps
        const float* Ah = sAh[cur];
        const float* Al = sAl[cur];
        const float* Bh = sBh[cur];
        const float* Bl = sBl[cur];
        #pragma unroll
        for (int kk = 0; kk < 32; kk += 8) {
            const int ka = kk + t;
            uint32_t ah0 = __float_as_uint(Ah[ rowA      * SA + ka    ]);
            uint32_t ah1 = __float_as_uint(Ah[(rowA + 8) * SA + ka    ]);
            uint32_t ah2 = __float_as_uint(Ah[ rowA      * SA + ka + 4]);
            uint32_t ah3 = __float_as_uint(Ah[(rowA + 8) * SA + ka + 4]);
            uint32_t al0 = __float_as_uint(Al[ rowA      * SA + ka    ]);
            uint32_t al1 = __float_as_uint(Al[(rowA + 8) * SA + ka    ]);
            uint32_t al2 = __float_as_uint(Al[ rowA      * SA + ka + 4]);
            uint32_t al3 = __float_as_uint(Al[(rowA + 8) * SA + ka + 4]);

            uint32_t bh00 = __float_as_uint(Bh[(ka    ) * SB + colB    ]);
            uint32_t bh01 = __float_as_uint(Bh[(ka + 4) * SB + colB    ]);
            uint32_t bh10 = __float_as_uint(Bh[(ka    ) * SB + colB + 8]);
            uint32_t bh11 = __float_as_uint(Bh[(ka + 4) * SB + colB + 8]);
            uint32_t bl00 = __float_as_uint(Bl[(ka    ) * SB + colB    ]);
            uint32_t bl01 = __float_as_uint(Bl[(ka + 4) * SB + colB    ]);
            uint32_t bl10 = __float_as_uint(Bl[(ka    ) * SB + colB + 8]);
            uint32_t bl11 = __float_as_uint(Bl[(ka + 4) * SB + colB + 8]);

            MMA_TF32(acc[0], ah0, ah1, ah2, ah3, bh00, bh01);
            MMA_TF32(acc[1], ah0, ah1, ah2, ah3, bh10, bh11);
            MMA_TF32(acc[0], al0, al1, al2, al3, bh00, bh01);
            MMA_TF32(acc[1], al0, al1, al2, al3, bh10, bh11);
            MMA_TF32(acc[0], ah0, ah1, ah2, ah3, bl00, bl01);
            MMA_TF32(acc[1], ah0, ah1, ah2, ah3, bl10, bl11);
        }

        // split + store prefetched tile
        if (tt < 15) {
            float h0,l0,h1,l1,h2,l2,h3,l3;
            cvt_split(va.x, h0, l0); cvt_split(va.y, h1, l1);
            cvt_split(va.z, h2, l2); cvt_split(va.w, h3, l3);
            float* ah = &sAh[nxt][ar * SA + ac4 * 4];
            float* al = &sAl[nxt][ar * SA + ac4 * 4];
            ah[0]=h0; ah[1]=h1; ah[2]=h2; ah[3]=h3;
            al[0]=l0; al[1]=l1; al[2]=l2; al[3]=l3;

            cvt_split(vb0.x, h0, l0); cvt_split(vb0.y, h1, l1);
            cvt_split(vb0.z, h2, l2); cvt_split(vb0.w, h3, l3);
            float* bh = &sBh[nxt][br * SB + bc4 * 4];
            float* bl = &sBl[nxt][br * SB + bc4 * 4];
            bh[0]=h0; bh[1]=h1; bh[2]=h2; bh[3]=h3;
            bl[0]=l0; bl[1]=l1; bl[2]=l2; bl[3]=l3;
            cvt_split(vb1.x, h0, l0); cvt_split(vb1.y, h1, l1);
            cvt_split(vb1.z, h2, l2); cvt_split(vb1.w, h3, l3);
            bh = &sBh[nxt][(br + 16) * SB + bc4 * 4];
            bl = &sBl[nxt][(br + 16) * SB + bc4 * 4];
            bh[0]=h0; bh[1]=h1; bh[2]=h2; bh[3]=h3;
            bl[0]=l0; bl[1]=l1; bl[2]=l2; bl[3]=l3;
        }
        __syncthreads();
    }

    // ---- epilogue: write h1 + fused es1/ed1 ----
    const int r0 = m0 + wm * 16 + g;
    const int r1 = r0 + 8;
    // cols: tile0 -> wn*16 + 2t,2t+1 ; tile1 -> wn*16 + 8 + 2t,2t+1
    #pragma unroll
    for (int tl = 0; tl < 2; tl++) {
        const int c0 = wn * 16 + tl * 8 + 2 * t;
        *(float2*)(g_h1 + (size_t)r0 * HD1 + c0) = make_float2(acc[tl][0], acc[tl][1]);
        *(float2*)(g_h1 + (size_t)r1 * HD1 + c0) = make_float2(acc[tl][2], acc[tl][3]);
    }

    #pragma unroll
    for (int tl = 0; tl < 2; tl++) {
        const int c0 = wn * 16 + tl * 8 + 2 * t;
        const int h  = 2 * wn + tl;
        const float as0 = __ldg(&a_src[c0]),  as1 = __ldg(&a_src[c0 + 1]);
        const float ad0 = __ldg(&a_dst[c0]),  ad1 = __ldg(&a_dst[c0 + 1]);
        float sr0 = acc[tl][0] * as0 + acc[tl][1] * as1;
        float sr1 = acc[tl][2] * as0 + acc[tl][3] * as1;
        float dr0 = acc[tl][0] * ad0 + acc[tl][1] * ad1;
        float dr1 = acc[tl][2] * ad0 + acc[tl][3] * ad1;
        sr0 += __shfl_xor_sync(0xFFFFFFFFu, sr0, 1);
        sr0 += __shfl_xor_sync(0xFFFFFFFFu, sr0, 2);
        sr1 += __shfl_xor_sync(0xFFFFFFFFu, sr1, 1);
        sr1 += __shfl_xor_sync(0xFFFFFFFFu, sr1, 2);
        dr0 += __shfl_xor_sync(0xFFFFFFFFu, dr0, 1);
        dr0 += __shfl_xor_sync(0xFFFFFFFFu, dr0, 2);
        dr1 += __shfl_xor_sync(0xFFFFFFFFu, dr1, 1);
        dr1 += __shfl_xor_sync(0xFFFFFFFFu, dr1, 2);
        if (t == 0) {
            g_es1[r0 * NH1 + h] = sr0;
            g_es1[r1 * NH1 + h] = sr1;
            g_ed1[r0 * NH1 + h] = dr0;
            g_ed1[r1 * NH1 + h] = dr1;
        }
    }
}

// ---------------------------------------------------------------------------
// K2: FUSED adjacency-scan + layer-1 attention + ELU + layer-2 row + scores.
// (round-13, unchanged)
// ---------------------------------------------------------------------------
__global__ __launch_bounds__(64) void k_attn1(const void* __restrict__ adj,
                                              const float* __restrict__ W2,
                                              const float* __restrict__ a2_src,
                                              const float* __restrict__ a2_dst)
{
    const int i    = blockIdx.x;
    const int tid  = threadIdx.x;
    const int lane = tid & 31;
    const int wid  = tid >> 5;
    const uint8_t* u8 = (const uint8_t*)adj;

    __shared__ int   snbr[MAXDEG];
    __shared__ float ew[MAXDEG * NH1];
    __shared__ float red[2][NH1];
    __shared__ float ssv[NH1];
    __shared__ float sa1[HD1];
    __shared__ int   wsum[2];

    int fmt;
    if (u8[(size_t)N_NODES + 1] == 1)            fmt = 0;
    else if (u8[4 * ((size_t)N_NODES + 1)] == 1) fmt = 1;
    else                                         fmt = 2;

    uint64_t mask = 0;
    #pragma unroll
    for (int r = 0; r < 16; r++) {
        const int cbase = (r * 64 + tid) * 4;
        uint64_t p0, p1, p2, p3;
        if (fmt == 2) {
            float4 v = *(const float4*)((const float*)adj + (size_t)i * N_NODES + cbase);
            p0 = v.x != 0.f; p1 = v.y != 0.f; p2 = v.z != 0.f; p3 = v.w != 0.f;
        } else if (fmt == 1) {
            int4 v = *(const int4*)((const int*)adj + (size_t)i * N_NODES + cbase);
            p0 = v.x != 0; p1 = v.y != 0; p2 = v.z != 0; p3 = v.w != 0;
        } else {
            uint32_t w = *(const uint32_t*)(u8 + (size_t)i * N_NODES + cbase);
            p0 = (w & 0x000000FFu) != 0;
            p1 = (w & 0x0000FF00u) != 0;
            p2 = (w & 0x00FF0000u) != 0;
            p3 = (w & 0xFF000000u) != 0;
        }
        mask |= (p0 << (r * 4)) | (p1 << (r * 4 + 1)) |
                (p2 << (r * 4 + 2)) | (p3 << (r * 4 + 3));
    }
    const int cnt = (int)__popcll(mask);

    int incl = cnt;
    #pragma unroll
    for (int o = 1; o < 32; o <<= 1) {
        int t = __shfl_up_sync(0xFFFFFFFFu, incl, o);
        if (lane >= o) incl += t;
    }
    if (lane == 31) wsum[wid] = incl;
    __syncthreads();
    const int total = wsum[0] + wsum[1];
    const int deg   = (total > MAXDEG) ? MAXDEG : total;
    if (tid == 0) g_deg[i] = deg;

    {
        int base = ((wid == 1) ? wsum[0] : 0) + (incl - cnt);
        int* gout = g_nbr + (size_t)i * MAXDEG;
        #pragma unroll
        for (int r = 0; r < 16; r++) {
            const int cbase = (r * 64 + tid) * 4;
            #pragma unroll
            for (int q = 0; q < 4; q++) {
                if ((mask >> (r * 4 + q)) & 1ull) {
                    if (base < MAXDEG) {
                        snbr[base] = cbase + q;
                        gout[base] = cbase + q;
                    }
                    base++;
                }
            }
        }
    }
    __syncthreads();

    const int h  = tid & 7;
    const int wh = tid >> 5;
    const int tot = deg * NH1;
    const float esi_h = g_es1[i * NH1 + h];

    float sloc = 0.f;
    for (int idx = tid; idx < tot; idx += 64) {
        int j = idx >> 3;
        float e = esi_h + g_ed1[snbr[j] * NH1 + h];
        e = (e > 0.f) ? e : 0.2f * e;
        float w = __expf(e);
        ew[idx] = w;
        sloc += w;
    }
    sloc += __shfl_xor_sync(0xFFFFFFFFu, sloc, 8);
    sloc += __shfl_xor_sync(0xFFFFFFFFu, sloc, 16);
    if ((tid & 31) < 8) red[wh][h] = sloc;
    __syncthreads();
    if (tid < NH1) ssv[tid] = 1.f / (red[0][tid] + red[1][tid]);
    __syncthreads();

    {
        const int hh = tid >> 3;
        const float inv = ssv[hh];
        float a0 = 0.f, a1 = 0.f, a2 = 0.f, a3 = 0.f;
        int j = 0;
        for (; j + 4 <= deg; j += 4) {
            a0 += ew[(j+0) * NH1 + hh] * g_h1[(size_t)snbr[j+0] * HD1 + tid];
            a1 += ew[(j+1) * NH1 + hh] * g_h1[(size_t)snbr[j+1] * HD1 + tid];
            a2 += ew[(j+2) * NH1 + hh] * g_h1[(size_t)snbr[j+2] * HD1 + tid];
            a3 += ew[(j+3) * NH1 + hh] * g_h1[(size_t)snbr[j+3] * HD1 + tid];
        }
        for (; j < deg; j++)
            a0 += ew[j * NH1 + hh] * g_h1[(size_t)snbr[j] * HD1 + tid];
        float acc = ((a0 + a1) + (a2 + a3)) * inv;
        acc = (acc > 0.f) ? acc : expm1f(acc);   // ELU
        sa1[tid] = acc;
    }
    __syncthreads();

    if (tid < C2) {
        float v = 0.f;
        #pragma unroll 8
        for (int k = 0; k < HD1; k++)
            v += sa1[k] * __ldg(&W2[k * C2 + tid]);
        g_h2[(size_t)i * C2 + tid] = v;

        float s = v * a2_src[tid];
        float d = v * a2_dst[tid];
        #pragma unroll
        for (int o = 8; o >= 1; o >>= 1) {
            s += __shfl_xor_sync(0x0000FFFFu, s, o);
            d += __shfl_xor_sync(0x0000FFFFu, d, o);
        }
        if (tid == 0) {
            g_es2[i] = s;
            g_ed2[i] = d;
        }
    }
}

// ---------------------------------------------------------------------------
// K3: layer-2 sparse attention. Single fused pass (unchanged).
// ---------------------------------------------------------------------------
__global__ __launch_bounds__(256) void k_attn2(float* __restrict__ out)
{
    const int w    = threadIdx.x >> 5;
    const int lane = threadIdx.x & 31;
    const int i    = blockIdx.x * 8 + w;
    const int deg  = g_deg[i];

    __shared__ int snbr[8][MAXDEG];

    for (int j = lane; j < deg; j += 32)
        snbr[w][j] = g_nbr[(size_t)i * MAXDEG + j];
    __syncwarp();

    const float esi = g_es2[i];
    const int g  = lane >> 2;
    const int c4 = lane & 3;

    float4 acc = make_float4(0.f, 0.f, 0.f, 0.f);
    float  wsum = 0.f;
    for (int base = 0; base < deg; base += 8) {
        int j = base + g;
        if (j < deg) {
            int   n  = snbr[w][j];
            float e  = esi + g_ed2[n];
            e = (e > 0.f) ? e : 0.2f * e;
            float wt = __expf(e);
            float4 v = *(const float4*)(g_h2 + (size_t)n * C2 + c4 * 4);
            acc.x += wt * v.x;
            acc.y += wt * v.y;
            acc.z += wt * v.z;
            acc.w += wt * v.w;
            wsum  += wt;
        }
    }
    #pragma unroll
    for (int o = 4; o <= 16; o <<= 1) {
        acc.x += __shfl_xor_sync(0xFFFFFFFFu, acc.x, o);
        acc.y += __shfl_xor_sync(0xFFFFFFFFu, acc.y, o);
        acc.z += __shfl_xor_sync(0xFFFFFFFFu, acc.z, o);
        acc.w += __shfl_xor_sync(0xFFFFFFFFu, acc.w, o);
        wsum  += __shfl_xor_sync(0xFFFFFFFFu, wsum,  o);
    }
    if (lane < 4) {
        const float inv = 1.f / wsum;
        float4 r = make_float4(acc.x * inv, acc.y * inv, acc.z * inv, acc.w * inv);
        *(float4*)(out + (size_t)i * C2 + lane * 4) = r;
    }
}

// ---------------------------------------------------------------------------
// Launch: strictly sequential on the capture stream. 3 kernels.
// ---------------------------------------------------------------------------
extern "C" void kernel_launch(void* const* d_in, const int* in_sizes, int n_in,
                              void* d_out, int out_size)
{
    const float* x      = (const float*)d_in[0];
    const void*  adj    = d_in[1];
    const float* W1     = (const float*)d_in[2];
    const float* a1_src = (const float*)d_in[3];
    const float* a1_dst = (const float*)d_in[4];
    const float* W2     = (const float*)d_in[5];
    const float* a2_src = (const float*)d_in[6];
    const float* a2_dst = (const float*)d_in[7];
    float* out = (float*)d_out;

    k_gemm1<<<N_NODES / 32, 256>>>(x, W1, a1_src, a1_dst);
    k_attn1<<<N_NODES, 64>>>(adj, W2, a2_src, a2_dst);
    k_attn2<<<N_NODES / 8, 256>>>(out);
}